// round 3
// baseline (speedup 1.0000x reference)
#include <cuda_runtime.h>
#include <cuda_bf16.h>

#define Bn 8
#define Nn 2048
#define Mn 256
#define Qn 16384
#define Dn 32
#define Rn 16
#define Kn 16
#define Hn 64
#define LAMf 5.0f
#define CG_ITERS 20

// ---------------- device scratch (no allocations allowed) ----------------
__device__ float g_gvec[Bn * Dn];
__device__ float g_c0s[Bn * Mn * Dn];
__device__ float g_cs[Bn * Mn * Dn];

__device__ __forceinline__ float dot4(float4 a, float4 b) {
    return a.x * b.x + a.y * b.y + a.z * b.z + a.w * b.w;
}

// ---------------- global feature g[b,:] ----------------
__global__ __launch_bounds__(256) void k_g(const float* __restrict__ xs,
                                           const float* __restrict__ us,
                                           const float* __restrict__ Wg1,
                                           const float* __restrict__ bg1,
                                           const float* __restrict__ Wg2,
                                           const float* __restrict__ bg2) {
    __shared__ float part[256];
    __shared__ float gmean[Hn];
    int b = blockIdx.x;
    int t = threadIdx.x;
    int h = t & 63, grp = t >> 6;
    float w0 = Wg1[h], w1 = Wg1[Hn + h], bb = bg1[h];
    float acc = 0.f;
    for (int n = grp; n < Nn; n += 4) {
        float v = fmaf(xs[b * Nn + n], w0, fmaf(us[b * Nn + n], w1, bb));
        acc += fmaxf(v, 0.f);
    }
    part[t] = acc;
    __syncthreads();
    if (t < Hn)
        gmean[t] = (part[t] + part[t + 64] + part[t + 128] + part[t + 192]) * (1.0f / (float)Nn);
    __syncthreads();
    if (t < Dn) {
        float a = bg2[t];
#pragma unroll
        for (int hh = 0; hh < Hn; hh++) a = fmaf(gmean[hh], Wg2[hh * Dn + t], a);
        g_gvec[b * Dn + t] = a;
    }
}

// ---------------- encoder: c0[b,m,:] (block per (b,m), 64 threads = H) ----------------
__global__ __launch_bounds__(64) void k_encode(const float* __restrict__ xs,
                                               const float* __restrict__ us,
                                               const float* __restrict__ centers,
                                               const float* __restrict__ W1,
                                               const float* __restrict__ b1,
                                               const float* __restrict__ W2,
                                               const float* __restrict__ b2,
                                               const float* __restrict__ W3,
                                               const float* __restrict__ b3,
                                               const int* __restrict__ idx,
                                               float* __restrict__ out_c0) {
    __shared__ float W2s[Hn * Hn];
    __shared__ float h1[Kn][Hn];
    __shared__ float sx[Kn], su[Kn];
    __shared__ float hm[Hn];
    int bm = blockIdx.x;
    int b = bm >> 8, m = bm & 255;
    int t = threadIdx.x;  // h index

    for (int i = t; i < Hn * Hn; i += 64) W2s[i] = W2[i];
    if (t < Kn) {
        int id = idx[m * Kn + t];
        sx[t] = xs[b * Nn + id];
        su[t] = us[b * Nn + id];
    }
    __syncthreads();

    const float invR = (float)Mn / 1.5f;  // 1/RADIUS
    float w1a = W1[t], w1b = W1[Hn + t], bb1 = b1[t];
    float cm = centers[m];
#pragma unroll
    for (int k = 0; k < Kn; k++) {
        float rel = (sx[k] - cm) * invR;
        h1[k][t] = fmaxf(fmaf(rel, w1a, fmaf(su[k], w1b, bb1)), 0.f);
    }
    __syncthreads();

    float bb2 = b2[t];
    float accv[Kn];
#pragma unroll
    for (int k = 0; k < Kn; k++) accv[k] = bb2;
#pragma unroll
    for (int hh = 0; hh < Hn; hh += 4) {
        float wa = W2s[(hh + 0) * Hn + t];
        float wb = W2s[(hh + 1) * Hn + t];
        float wc = W2s[(hh + 2) * Hn + t];
        float wd = W2s[(hh + 3) * Hn + t];
#pragma unroll
        for (int k = 0; k < Kn; k++) {
            float4 hv = *(const float4*)&h1[k][hh];
            accv[k] = fmaf(hv.x, wa, accv[k]);
            accv[k] = fmaf(hv.y, wb, accv[k]);
            accv[k] = fmaf(hv.z, wc, accv[k]);
            accv[k] = fmaf(hv.w, wd, accv[k]);
        }
    }
    float ssum = 0.f;
#pragma unroll
    for (int k = 0; k < Kn; k++) ssum += fmaxf(accv[k], 0.f);
    hm[t] = ssum * (1.0f / (float)Kn);
    __syncthreads();

    if (t < Dn) {
        float a = b3[t];
#pragma unroll
        for (int hh = 0; hh < Hn; hh++) a = fmaf(hm[hh], W3[hh * Dn + t], a);
        a += g_gvec[b * Dn + t];
        int gi = (b * Mn + m) * Dn + t;
        g_c0s[gi] = a;
        out_c0[gi] = a;
    }
}

// ---------------- CG glue: one CTA per batch, 512 threads, syncthreads only ----------------
// smem layout (floats): p[8192] | re[4080] | red[16] | bcast[2]
#define CG_SM_P 0
#define CG_SM_RE 8192
#define CG_SM_RED (8192 + 4080)
#define CG_SM_BC (8192 + 4080 + 16)
#define CG_SM_FLOATS (8192 + 4080 + 16 + 2)

__global__ __launch_bounds__(512, 1) void k_cg(const float* __restrict__ Rsrc,
                                               const float* __restrict__ Rdst,
                                               float* __restrict__ out_c) {
    extern __shared__ float sm[];
    float* p_sm = sm + CG_SM_P;
    float* re_sm = sm + CG_SM_RE;
    float* red = sm + CG_SM_RED;
    float* bcast = sm + CG_SM_BC;

    const int b = blockIdx.x;
    const int t = threadIdx.x;
    const int lane = t & 31;
    const int warp = t >> 5;

    // thread owns 4 float4 columns: col = t + 512*k ; element index = col*4
    float4 x4[4], r4[4], p4[4], Ap[4];

    const float* c0p = g_c0s + b * (Mn * Dn);

#pragma unroll
    for (int k = 0; k < 4; k++) {
        int col = t + 512 * k;
        float4 v = *(const float4*)(c0p + col * 4);
        x4[k] = v;
        p4[k] = v;
        *(float4*)(p_sm + col * 4) = v;
    }
    __syncthreads();

    // reduction helper (inlined via lambda)
    auto block_sum = [&](float v) -> float {
#pragma unroll
        for (int o = 16; o > 0; o >>= 1) v += __shfl_xor_sync(0xffffffffu, v, o);
        if (lane == 0) red[warp] = v;
        __syncthreads();
        if (warp == 0) {
            float s = (lane < 16) ? red[lane] : 0.f;
#pragma unroll
            for (int o = 8; o > 0; o >>= 1) s += __shfl_xor_sync(0xffffffffu, s, o);
            if (lane == 0) bcast[0] = s;
        }
        __syncthreads();
        return bcast[0];
    };

    // A(p) into Ap[] registers; reads p_sm (all) and p4 (own)
    auto applyA = [&]() {
        // phase A: edge residuals re[e,rho] = sum_d Rs[e,rho,d]*p[e,d] - Rd[e,rho,d]*p[e+1,d]
#pragma unroll
        for (int gi = 0; gi < 2; gi++) {
            int g = t + gi * 512;
            if (g < 1020) {
                int e = g >> 2, rb = g & 3;
                const float4* RS = (const float4*)(Rsrc + (size_t)e * 512);
                const float4* RD = (const float4*)(Rdst + (size_t)e * 512);
                const float4* PE = (const float4*)(p_sm + e * 32);
                float a0 = 0.f, a1 = 0.f, a2 = 0.f, a3 = 0.f;
#pragma unroll
                for (int j = 0; j < 8; j++) {
                    float4 pv = PE[j];
                    float4 qv = PE[8 + j];
                    float4 s;
                    s = RS[(rb + 0) * 8 + j]; a0 += dot4(s, pv);
                    s = RD[(rb + 0) * 8 + j]; a0 -= dot4(s, qv);
                    s = RS[(rb + 4) * 8 + j]; a1 += dot4(s, pv);
                    s = RD[(rb + 4) * 8 + j]; a1 -= dot4(s, qv);
                    s = RS[(rb + 8) * 8 + j]; a2 += dot4(s, pv);
                    s = RD[(rb + 8) * 8 + j]; a2 -= dot4(s, qv);
                    s = RS[(rb + 12) * 8 + j]; a3 += dot4(s, pv);
                    s = RD[(rb + 12) * 8 + j]; a3 -= dot4(s, qv);
                }
                re_sm[e * 16 + rb + 0] = a0;
                re_sm[e * 16 + rb + 4] = a1;
                re_sm[e * 16 + rb + 8] = a2;
                re_sm[e * 16 + rb + 12] = a3;
            }
        }
        __syncthreads();

        // phase B: Ap[m,d] = p[m,d] + LAM*( [m<255] Rs[m]^T re[m] - [m>0] Rd[m-1]^T re[m-1] )
#pragma unroll
        for (int k = 0; k < 4; k++) {
            int col = t + 512 * k;
            int m = col >> 3, d4 = col & 7;
            float4 acc = make_float4(0.f, 0.f, 0.f, 0.f);
            if (m < Mn - 1) {
                const float4* RS = (const float4*)(Rsrc + (size_t)m * 512) + d4;
                const float* REm = re_sm + m * 16;
#pragma unroll
                for (int rho = 0; rho < 16; rho++) {
                    float4 rv = RS[rho * 8];
                    float wv = REm[rho];
                    acc.x += rv.x * wv; acc.y += rv.y * wv;
                    acc.z += rv.z * wv; acc.w += rv.w * wv;
                }
            }
            if (m > 0) {
                const float4* RD = (const float4*)(Rdst + (size_t)(m - 1) * 512) + d4;
                const float* REm = re_sm + (m - 1) * 16;
#pragma unroll
                for (int rho = 0; rho < 16; rho++) {
                    float4 rv = RD[rho * 8];
                    float wv = REm[rho];
                    acc.x -= rv.x * wv; acc.y -= rv.y * wv;
                    acc.z -= rv.z * wv; acc.w -= rv.w * wv;
                }
            }
            Ap[k].x = p4[k].x + LAMf * acc.x;
            Ap[k].y = p4[k].y + LAMf * acc.y;
            Ap[k].z = p4[k].z + LAMf * acc.z;
            Ap[k].w = p4[k].w + LAMf * acc.w;
        }
    };

    // r = c0 - A(c0); p = r; rs = <r,r>
    applyA();
    float lsum = 0.f;
#pragma unroll
    for (int k = 0; k < 4; k++) {
        r4[k].x = x4[k].x - Ap[k].x;
        r4[k].y = x4[k].y - Ap[k].y;
        r4[k].z = x4[k].z - Ap[k].z;
        r4[k].w = x4[k].w - Ap[k].w;
        p4[k] = r4[k];
        lsum += dot4(r4[k], r4[k]);
    }
    float rs = block_sum(lsum);
    // publish p into p_sm
#pragma unroll
    for (int k = 0; k < 4; k++) {
        int col = t + 512 * k;
        *(float4*)(p_sm + col * 4) = p4[k];
    }
    __syncthreads();

    for (int it = 0; it < CG_ITERS; it++) {
        applyA();
        float pap_l = 0.f;
#pragma unroll
        for (int k = 0; k < 4; k++) pap_l += dot4(p4[k], Ap[k]);
        float pap = block_sum(pap_l);
        float alpha = rs / (pap + 1e-12f);

        float rs_l = 0.f;
#pragma unroll
        for (int k = 0; k < 4; k++) {
            x4[k].x = fmaf(alpha, p4[k].x, x4[k].x);
            x4[k].y = fmaf(alpha, p4[k].y, x4[k].y);
            x4[k].z = fmaf(alpha, p4[k].z, x4[k].z);
            x4[k].w = fmaf(alpha, p4[k].w, x4[k].w);
            r4[k].x = fmaf(-alpha, Ap[k].x, r4[k].x);
            r4[k].y = fmaf(-alpha, Ap[k].y, r4[k].y);
            r4[k].z = fmaf(-alpha, Ap[k].z, r4[k].z);
            r4[k].w = fmaf(-alpha, Ap[k].w, r4[k].w);
            rs_l += dot4(r4[k], r4[k]);
        }
        float rs_new = block_sum(rs_l);
        float beta = rs_new / (rs + 1e-12f);
        rs = rs_new;
#pragma unroll
        for (int k = 0; k < 4; k++) {
            p4[k].x = fmaf(beta, p4[k].x, r4[k].x);
            p4[k].y = fmaf(beta, p4[k].y, r4[k].y);
            p4[k].z = fmaf(beta, p4[k].z, r4[k].z);
            p4[k].w = fmaf(beta, p4[k].w, r4[k].w);
            int col = t + 512 * k;
            *(float4*)(p_sm + col * 4) = p4[k];
        }
        __syncthreads();
    }

    // write final c
    float* gc = g_cs + b * (Mn * Dn);
    float* oc = out_c + b * (Mn * Dn);
#pragma unroll
    for (int k = 0; k < 4; k++) {
        int col = t + 512 * k;
        *(float4*)(gc + col * 4) = x4[k];
        *(float4*)(oc + col * 4) = x4[k];
    }
}

// ---------------- decode: s_pred[b,q] = sum_m w[m,q] * <phi[m,q,:], c[b,m,:]> ----------------
// support of w/phi is only m in {q/64 - 1, q/64, q/64 + 1}
__global__ __launch_bounds__(128) void k_decode(const float* __restrict__ phi,
                                                const float* __restrict__ w,
                                                float* __restrict__ out_s) {
    __shared__ float csm[Bn][4][Dn];
    int qbase = blockIdx.x * 128;
    int mlo = (qbase >> 6) - 1;
    int t = threadIdx.x;

    for (int i = t; i < Bn * 4 * Dn; i += 128) {
        int b = i >> 7;
        int mi = (i >> 5) & 3;
        int d = i & 31;
        int m = mlo + mi;
        csm[b][mi][d] = (m >= 0 && m < Mn) ? g_cs[(b * Mn + m) * Dn + d] : 0.f;
    }
    __syncthreads();

    int q = qbase + t;
    int mq = q >> 6;
    float acc[Bn];
#pragma unroll
    for (int b = 0; b < Bn; b++) acc[b] = 0.f;

#pragma unroll
    for (int kk = 0; kk < 3; kk++) {
        int m = mq - 1 + kk;
        if (m < 0 || m >= Mn) continue;
        float wv = w[(size_t)m * Qn + q];
        int mi = m - mlo;
        const float4* ph = (const float4*)(phi + ((size_t)m * Qn + q) * Dn);
        float dotb[Bn];
#pragma unroll
        for (int b = 0; b < Bn; b++) dotb[b] = 0.f;
#pragma unroll
        for (int j = 0; j < 8; j++) {
            float4 pv = ph[j];
#pragma unroll
            for (int b = 0; b < Bn; b++) {
                float4 cc = *(const float4*)&csm[b][mi][j * 4];
                dotb[b] += dot4(pv, cc);
            }
        }
#pragma unroll
        for (int b = 0; b < Bn; b++) acc[b] = fmaf(wv, dotb[b], acc[b]);
    }
#pragma unroll
    for (int b = 0; b < Bn; b++) out_s[b * Qn + q] = acc[b];
}

// ---------------- launch ----------------
extern "C" void kernel_launch(void* const* d_in, const int* in_sizes, int n_in,
                              void* d_out, int out_size) {
    const float* xs = (const float*)d_in[0];
    const float* us = (const float*)d_in[1];
    const float* phi_q = (const float*)d_in[2];
    const float* w = (const float*)d_in[3];
    const float* centers = (const float*)d_in[4];
    const float* R_src = (const float*)d_in[5];
    const float* R_dst = (const float*)d_in[6];
    const float* W1 = (const float*)d_in[7];
    const float* b1 = (const float*)d_in[8];
    const float* W2 = (const float*)d_in[9];
    const float* b2 = (const float*)d_in[10];
    const float* W3 = (const float*)d_in[11];
    const float* b3 = (const float*)d_in[12];
    const float* Wg1 = (const float*)d_in[13];
    const float* bg1 = (const float*)d_in[14];
    const float* Wg2 = (const float*)d_in[15];
    const float* bg2 = (const float*)d_in[16];
    const int* idx = (const int*)d_in[17];

    float* out = (float*)d_out;
    float* out_s = out;                         // [B,Q,1]
    float* out_c0 = out + Bn * Qn;              // [B,M,D]
    float* out_c = out + Bn * Qn + Bn * Mn * Dn;  // [B,M,D]

    static int smem_set = 0;
    if (!smem_set) {
        cudaFuncSetAttribute(k_cg, cudaFuncAttributeMaxDynamicSharedMemorySize,
                             CG_SM_FLOATS * (int)sizeof(float));
        smem_set = 1;
    }

    k_g<<<Bn, 256>>>(xs, us, Wg1, bg1, Wg2, bg2);
    k_encode<<<Bn * Mn, 64>>>(xs, us, centers, W1, b1, W2, b2, W3, b3, idx, out_c0);
    k_cg<<<Bn, 512, CG_SM_FLOATS * sizeof(float)>>>(R_src, R_dst, out_c);
    k_decode<<<Qn / 128, 128>>>(phi_q, w, out_s);
}

// round 4
// speedup vs baseline: 5.1888x; 5.1888x over previous
#include <cuda_runtime.h>
#include <cuda_bf16.h>
#include <cooperative_groups.h>

namespace cg = cooperative_groups;

#define Bn 8
#define Nn 2048
#define Mn 256
#define Qn 16384
#define Dn 32
#define Rn 16
#define Kn 16
#define Hn 64
#define LAMf 5.0f
#define CG_ITERS 20

// ---------------- device scratch (no allocations allowed) ----------------
__device__ float g_gvec[Bn * Dn];
__device__ float g_c0s[Bn * Mn * Dn];
__device__ float g_cs[Bn * Mn * Dn];

__device__ __forceinline__ float dot4(float4 a, float4 b) {
    return a.x * b.x + a.y * b.y + a.z * b.z + a.w * b.w;
}

// ---------------- global feature g[b,:] ----------------
__global__ __launch_bounds__(256) void k_g(const float* __restrict__ xs,
                                           const float* __restrict__ us,
                                           const float* __restrict__ Wg1,
                                           const float* __restrict__ bg1,
                                           const float* __restrict__ Wg2,
                                           const float* __restrict__ bg2) {
    __shared__ float part[256];
    __shared__ float gmean[Hn];
    int b = blockIdx.x;
    int t = threadIdx.x;
    int h = t & 63, grp = t >> 6;
    float w0 = Wg1[h], w1 = Wg1[Hn + h], bb = bg1[h];
    float acc = 0.f;
    for (int n = grp; n < Nn; n += 4) {
        float v = fmaf(xs[b * Nn + n], w0, fmaf(us[b * Nn + n], w1, bb));
        acc += fmaxf(v, 0.f);
    }
    part[t] = acc;
    __syncthreads();
    if (t < Hn)
        gmean[t] = (part[t] + part[t + 64] + part[t + 128] + part[t + 192]) * (1.0f / (float)Nn);
    __syncthreads();
    if (t < Dn) {
        float a = bg2[t];
#pragma unroll
        for (int hh = 0; hh < Hn; hh++) a = fmaf(gmean[hh], Wg2[hh * Dn + t], a);
        g_gvec[b * Dn + t] = a;
    }
}

// ---------------- encoder: c0[b,m,:] (block per (b,m), 64 threads = H) ----------------
__global__ __launch_bounds__(64) void k_encode(const float* __restrict__ xs,
                                               const float* __restrict__ us,
                                               const float* __restrict__ centers,
                                               const float* __restrict__ W1,
                                               const float* __restrict__ b1,
                                               const float* __restrict__ W2,
                                               const float* __restrict__ b2,
                                               const float* __restrict__ W3,
                                               const float* __restrict__ b3,
                                               const int* __restrict__ idx,
                                               float* __restrict__ out_c0) {
    __shared__ float W2s[Hn * Hn];
    __shared__ float h1[Kn][Hn];
    __shared__ float sx[Kn], su[Kn];
    __shared__ float hm[Hn];
    int bm = blockIdx.x;
    int b = bm >> 8, m = bm & 255;
    int t = threadIdx.x;  // h index

    for (int i = t; i < Hn * Hn; i += 64) W2s[i] = W2[i];
    if (t < Kn) {
        int id = idx[m * Kn + t];
        sx[t] = xs[b * Nn + id];
        su[t] = us[b * Nn + id];
    }
    __syncthreads();

    const float invR = (float)Mn / 1.5f;  // 1/RADIUS
    float w1a = W1[t], w1b = W1[Hn + t], bb1 = b1[t];
    float cm = centers[m];
#pragma unroll
    for (int k = 0; k < Kn; k++) {
        float rel = (sx[k] - cm) * invR;
        h1[k][t] = fmaxf(fmaf(rel, w1a, fmaf(su[k], w1b, bb1)), 0.f);
    }
    __syncthreads();

    float bb2 = b2[t];
    float accv[Kn];
#pragma unroll
    for (int k = 0; k < Kn; k++) accv[k] = bb2;
#pragma unroll
    for (int hh = 0; hh < Hn; hh += 4) {
        float wa = W2s[(hh + 0) * Hn + t];
        float wb = W2s[(hh + 1) * Hn + t];
        float wc = W2s[(hh + 2) * Hn + t];
        float wd = W2s[(hh + 3) * Hn + t];
#pragma unroll
        for (int k = 0; k < Kn; k++) {
            float4 hv = *(const float4*)&h1[k][hh];
            accv[k] = fmaf(hv.x, wa, accv[k]);
            accv[k] = fmaf(hv.y, wb, accv[k]);
            accv[k] = fmaf(hv.z, wc, accv[k]);
            accv[k] = fmaf(hv.w, wd, accv[k]);
        }
    }
    float ssum = 0.f;
#pragma unroll
    for (int k = 0; k < Kn; k++) ssum += fmaxf(accv[k], 0.f);
    hm[t] = ssum * (1.0f / (float)Kn);
    __syncthreads();

    if (t < Dn) {
        float a = b3[t];
#pragma unroll
        for (int hh = 0; hh < Hn; hh++) a = fmaf(hm[hh], W3[hh * Dn + t], a);
        a += g_gvec[b * Dn + t];
        int gi = (b * Mn + m) * Dn + t;
        g_c0s[gi] = a;
        out_c0[gi] = a;
    }
}

// ==================== CG glue: 8-CTA cluster per batch ====================
// grid = 64 CTAs, cluster (8,1,1). CTA rank s owns nodes [s*32, s*32+32),
// caches edges [s*32-1, s*32+31] (33 local edges, out-of-range zeroed) in smem.
// Local smem layout (floats):
#define OFF_RS 0
#define OFF_RD (33 * 512)
#define OFF_P (2 * 33 * 512)              // p on ext domain: 34 nodes (slot n = global s*32-1+n)
#define OFF_R (OFF_P + 34 * 32)           // r on ext domain: 34 nodes
#define OFF_RE (OFF_R + 34 * 32)          // edge residuals: 33 x 16
#define OFF_RED (OFF_RE + 33 * 16)        // 8 warp partials
#define OFF_SPAP (OFF_RED + 8)            // 8 cluster slots
#define OFF_SRS (OFF_SPAP + 8)            // 8 cluster slots
#define CG_SM_FLOATS (OFF_SRS + 8)

__device__ __forceinline__ float block_sum_all(float v, float* redsm) {
    int t = threadIdx.x;
#pragma unroll
    for (int o = 16; o > 0; o >>= 1) v += __shfl_xor_sync(0xffffffffu, v, o);
    __syncthreads();  // protect redsm reuse from previous call
    if ((t & 31) == 0) redsm[t >> 5] = v;
    __syncthreads();
    float s = 0.f;
#pragma unroll
    for (int w = 0; w < 8; w++) s += redsm[w];
    return s;
}

__device__ __forceinline__ float cluster_sum(float v, float* redsm, float* slots,
                                             cg::cluster_group& cl, int myrank) {
    float blk = block_sum_all(v, redsm);
    if (threadIdx.x < 8) {
        float* rem = cl.map_shared_rank(slots, (int)threadIdx.x);
        rem[myrank] = blk;
    }
    cl.sync();
    float s = 0.f;
#pragma unroll
    for (int rr = 0; rr < 8; rr++) s += slots[rr];
    return s;
}

__global__ void __cluster_dims__(8, 1, 1) __launch_bounds__(256, 1)
    k_cg(const float* __restrict__ Rsrc, const float* __restrict__ Rdst,
         float* __restrict__ out_c) {
    extern __shared__ float smf[];
    float4* Rs4 = (float4*)(smf + OFF_RS);
    float4* Rd4 = (float4*)(smf + OFF_RD);
    float4* p4s = (float4*)(smf + OFF_P);
    float4* r4s = (float4*)(smf + OFF_R);
    float* re_sm = smf + OFF_RE;
    float* redsm = smf + OFF_RED;
    float* spap = smf + OFF_SPAP;
    float* srs = smf + OFF_SRS;

    cg::cluster_group cl = cg::this_cluster();
    const int t = threadIdx.x;
    const int b = blockIdx.x >> 3;
    const int s = blockIdx.x & 7;  // cluster rank

    const int i = t >> 3;   // own node 0..31  (ext slot i+1)
    const int dq = t & 7;   // d-quad 0..7
    const float4 z4 = make_float4(0.f, 0.f, 0.f, 0.f);

    // ---- prologue: cache R slice ----
    const float4* Rsg = (const float4*)Rsrc;
    const float4* Rdg = (const float4*)Rdst;
    for (int i4 = t; i4 < 33 * 128; i4 += 256) {
        int le = i4 >> 7, rem = i4 & 127;
        int ge = s * 32 - 1 + le;
        bool ok = (ge >= 0) && (ge < Mn - 1);
        Rs4[i4] = ok ? Rsg[ge * 128 + rem] : z4;
        Rd4[i4] = ok ? Rdg[ge * 128 + rem] : z4;
    }
    // p = c0 on ext domain [s*32-1 .. s*32+32]
    const float4* c0g = (const float4*)g_c0s;
    for (int i4 = t; i4 < 34 * 8; i4 += 256) {
        int slot = i4 >> 3, j = i4 & 7;
        int gm = s * 32 - 1 + slot;
        p4s[i4] = (gm >= 0 && gm < Mn) ? c0g[(b * Mn + gm) * 8 + j] : z4;
    }
    __syncthreads();

    float4 x4 = p4s[(i + 1) * 8 + dq];  // x = c0 (own)
    float4 Ap;

    // applyA: reads p4s (ext), writes re_sm, produces Ap for own node (registers)
    auto applyA = [&]() {
        // phase A: re[le,rho] = Rs[le,rho,:].p[le] - Rd[le,rho,:].p[le+1]
        for (int ri = (t >> 3); ri < 33 * 16; ri += 32) {
            int le = ri >> 4, rho = ri & 15;
            float a = dot4(Rs4[le * 128 + rho * 8 + dq], p4s[le * 8 + dq]) -
                      dot4(Rd4[le * 128 + rho * 8 + dq], p4s[(le + 1) * 8 + dq]);
            a += __shfl_xor_sync(0xffffffffu, a, 1);
            a += __shfl_xor_sync(0xffffffffu, a, 2);
            a += __shfl_xor_sync(0xffffffffu, a, 4);
            if (dq == 0) re_sm[ri] = a;
        }
        __syncthreads();
        // phase B: Ap[own m=i] = p + LAM*( Rs[le=i+1]^T re[i+1] - Rd[le=i]^T re[i] )
        float4 acc = z4;
#pragma unroll
        for (int rho = 0; rho < 16; rho++) {
            float4 rv = Rs4[(i + 1) * 128 + rho * 8 + dq];
            float wv = re_sm[(i + 1) * 16 + rho];
            acc.x = fmaf(rv.x, wv, acc.x);
            acc.y = fmaf(rv.y, wv, acc.y);
            acc.z = fmaf(rv.z, wv, acc.z);
            acc.w = fmaf(rv.w, wv, acc.w);
        }
#pragma unroll
        for (int rho = 0; rho < 16; rho++) {
            float4 rv = Rd4[i * 128 + rho * 8 + dq];
            float wv = re_sm[i * 16 + rho];
            acc.x = fmaf(-rv.x, wv, acc.x);
            acc.y = fmaf(-rv.y, wv, acc.y);
            acc.z = fmaf(-rv.z, wv, acc.z);
            acc.w = fmaf(-rv.w, wv, acc.w);
        }
        float4 pown = p4s[(i + 1) * 8 + dq];
        Ap.x = fmaf(LAMf, acc.x, pown.x);
        Ap.y = fmaf(LAMf, acc.y, pown.y);
        Ap.z = fmaf(LAMf, acc.z, pown.z);
        Ap.w = fmaf(LAMf, acc.w, pown.w);
    };

    // fetch r halo nodes (slot 0 from left rank's node 31, slot 33 from right rank's node 0)
    auto fetch_r_halo = [&]() {
        if (t < 8) {
            if (s > 0) {
                const float4* rem = (const float4*)cl.map_shared_rank(smf + OFF_R, s - 1);
                r4s[t] = rem[32 * 8 + t];
            } else {
                r4s[t] = z4;
            }
        } else if (t < 16) {
            int j = t - 8;
            if (s < 7) {
                const float4* rem = (const float4*)cl.map_shared_rank(smf + OFF_R, s + 1);
                r4s[33 * 8 + j] = rem[1 * 8 + j];
            } else {
                r4s[33 * 8 + j] = z4;
            }
        }
        __syncthreads();
    };

    // ---- init: r = c0 - A(c0), p = r ----
    applyA();
    float4 rown = make_float4(x4.x - Ap.x, x4.y - Ap.y, x4.z - Ap.z, x4.w - Ap.w);
    r4s[(i + 1) * 8 + dq] = rown;
    float rs = cluster_sum(dot4(rown, rown), redsm, srs, cl, s);  // S0 also publishes r
    fetch_r_halo();
    for (int i4 = t; i4 < 34 * 8; i4 += 256) p4s[i4] = r4s[i4];

    // ---- main loop: 2 cluster syncs per iteration ----
    for (int it = 0; it < CG_ITERS; it++) {
        __syncthreads();  // p4s writes visible block-wide
        applyA();
        float4 pown = p4s[(i + 1) * 8 + dq];
        float pap = cluster_sum(dot4(pown, Ap), redsm, spap, cl, s);  // S2
        float alpha = rs / (pap + 1e-12f);

        x4.x = fmaf(alpha, pown.x, x4.x);
        x4.y = fmaf(alpha, pown.y, x4.y);
        x4.z = fmaf(alpha, pown.z, x4.z);
        x4.w = fmaf(alpha, pown.w, x4.w);
        rown = r4s[(i + 1) * 8 + dq];
        rown.x = fmaf(-alpha, Ap.x, rown.x);
        rown.y = fmaf(-alpha, Ap.y, rown.y);
        rown.z = fmaf(-alpha, Ap.z, rown.z);
        rown.w = fmaf(-alpha, Ap.w, rown.w);
        r4s[(i + 1) * 8 + dq] = rown;

        float rs_new = cluster_sum(dot4(rown, rown), redsm, srs, cl, s);  // S3, publishes r
        float beta = rs_new / (rs + 1e-12f);
        rs = rs_new;

        fetch_r_halo();
        // p = r + beta*p on full ext domain (halo p stays cluster-consistent: same beta)
        for (int i4 = t; i4 < 34 * 8; i4 += 256) {
            float4 rr = r4s[i4];
            float4 pp = p4s[i4];
            pp.x = fmaf(beta, pp.x, rr.x);
            pp.y = fmaf(beta, pp.y, rr.y);
            pp.z = fmaf(beta, pp.z, rr.z);
            pp.w = fmaf(beta, pp.w, rr.w);
            p4s[i4] = pp;
        }
    }

    // ---- write final c ----
    int gm = s * 32 + i;
    ((float4*)g_cs)[(b * Mn + gm) * 8 + dq] = x4;
    ((float4*)out_c)[(b * Mn + gm) * 8 + dq] = x4;
}

// ---------------- decode: s_pred[b,q] = sum_m w[m,q] * <phi[m,q,:], c[b,m,:]> ----------------
// support of w/phi is only m in {q/64 - 1, q/64, q/64 + 1}
// one block per 64-q group; 256 threads = 64 q x 4 batch-groups (2 batches each)
__global__ __launch_bounds__(256) void k_decode(const float* __restrict__ phi,
                                                const float* __restrict__ w,
                                                float* __restrict__ out_s) {
    __shared__ float csm[3][Bn][Dn];
    int g = blockIdx.x;  // q-group
    int qbase = g * 64;
    int mlo = g - 1;
    int t = threadIdx.x;

    for (int i = t; i < 3 * Bn * Dn; i += 256) {
        int mi = i >> 8;
        int b = (i >> 5) & 7;
        int d = i & 31;
        int m = mlo + mi;
        csm[mi][b][d] = (m >= 0 && m < Mn) ? g_cs[(b * Mn + m) * Dn + d] : 0.f;
    }
    __syncthreads();

    int q = qbase + (t & 63);
    int bg = t >> 6;  // 0..3 -> batches bg, bg+4
    float acc0 = 0.f, acc1 = 0.f;

#pragma unroll
    for (int kk = 0; kk < 3; kk++) {
        int m = mlo + kk;
        if (m < 0 || m >= Mn) continue;
        float wv = w[(size_t)m * Qn + q];
        const float4* ph = (const float4*)(phi + ((size_t)m * Qn + q) * Dn);
        const float4* c0 = (const float4*)&csm[kk][bg][0];
        const float4* c1 = (const float4*)&csm[kk][bg + 4][0];
        float d0 = 0.f, d1 = 0.f;
#pragma unroll
        for (int j = 0; j < 8; j++) {
            float4 pv = ph[j];
            d0 += dot4(pv, c0[j]);
            d1 += dot4(pv, c1[j]);
        }
        acc0 = fmaf(wv, d0, acc0);
        acc1 = fmaf(wv, d1, acc1);
    }
    out_s[bg * Qn + q] = acc0;
    out_s[(bg + 4) * Qn + q] = acc1;
}

// ---------------- launch ----------------
extern "C" void kernel_launch(void* const* d_in, const int* in_sizes, int n_in,
                              void* d_out, int out_size) {
    const float* xs = (const float*)d_in[0];
    const float* us = (const float*)d_in[1];
    const float* phi_q = (const float*)d_in[2];
    const float* w = (const float*)d_in[3];
    const float* centers = (const float*)d_in[4];
    const float* R_src = (const float*)d_in[5];
    const float* R_dst = (const float*)d_in[6];
    const float* W1 = (const float*)d_in[7];
    const float* b1 = (const float*)d_in[8];
    const float* W2 = (const float*)d_in[9];
    const float* b2 = (const float*)d_in[10];
    const float* W3 = (const float*)d_in[11];
    const float* b3 = (const float*)d_in[12];
    const float* Wg1 = (const float*)d_in[13];
    const float* bg1 = (const float*)d_in[14];
    const float* Wg2 = (const float*)d_in[15];
    const float* bg2 = (const float*)d_in[16];
    const int* idx = (const int*)d_in[17];

    float* out = (float*)d_out;
    float* out_s = out;                           // [B,Q,1]
    float* out_c0 = out + Bn * Qn;                // [B,M,D]
    float* out_c = out + Bn * Qn + Bn * Mn * Dn;  // [B,M,D]

    cudaFuncSetAttribute(k_cg, cudaFuncAttributeMaxDynamicSharedMemorySize,
                         CG_SM_FLOATS * (int)sizeof(float));

    k_g<<<Bn, 256>>>(xs, us, Wg1, bg1, Wg2, bg2);
    k_encode<<<Bn * Mn, 64>>>(xs, us, centers, W1, b1, W2, b2, W3, b3, idx, out_c0);
    k_cg<<<64, 256, CG_SM_FLOATS * sizeof(float)>>>(R_src, R_dst, out_c);
    k_decode<<<Qn / 64, 256>>>(phi_q, w, out_s);
}